// round 17
// baseline (speedup 1.0000x reference)
#include <cuda_runtime.h>
#include <cstdint>
#include <math.h>

#define N_SEQ   16384
#define TBL_N   64                 // intervals; TBL_N+1 knots
#define CHUNK   4096               // elements per map block
#define NTB     5                  // table blocks (16 knots each, 65 knots)

#define INP2 36                    // padded row widths (odd multiple of 16B)
#define INP3 68
#define INP4 68

// -------------------------- device scratch ---------------------------------
__device__ __align__(8)  float2 g_tbl2[TBL_N];      // (f[i], f[i+1]) pairs
__device__ __align__(16) float4 g_coef[TBL_N + 1];  // (A_i, B_i, C_i, 0): P(u)
__device__ float2 g_range;                          // (c0 = -lo*inv_h, inv_h)
__device__ int    g_cnt;                            // table blocks done

// -------------------------- math helpers -----------------------------------
__device__ __forceinline__ float splus(float x) {
    float e = __expf(-fabsf(x));
    return fmaxf(x, 0.0f) + __logf(1.0f + e);
}

// ---------------- kernel 1: range + f at knots + prefix ---------------------
__global__ __launch_bounds__(512) void table_kernel(
    const float* __restrict__ t, int nrows,
    const float* __restrict__ W1, const float* __restrict__ b1,
    const float* __restrict__ W2, const float* __restrict__ b2,
    const float* __restrict__ W3, const float* __restrict__ b3,
    const float* __restrict__ W4, const float* __restrict__ b4,
    const float* __restrict__ W5, const float* __restrict__ b5,
    int nblk)
{
    // let the dependent map kernel launch early (it prefetches t, then waits)
    cudaTriggerProgrammaticLaunchCompletion();

    __shared__ __align__(16) float sW2p[64 * INP2];
    __shared__ __align__(16) float sW3p[64 * INP3];
    __shared__ __align__(16) float sW4p[32 * INP4];
    __shared__ __align__(16) float hbuf[16][2][64];   // [warp][pingpong][unit]
    __shared__ float sW1[32], sB1[32], sB2[64], sB3[64], sB4[32], sW5[32];
    __shared__ float sB5;
    __shared__ float s_a[16], s_b[16];
    __shared__ float s_lo, s_h;
    __shared__ int   s_last;

    int tid = threadIdx.x;
    int wid = tid >> 5, lane = tid & 31;
    const unsigned m = 0xffffffffu;

    // ---- stage weights (coalesced; padded rows -> conflict-free LDS.128)
    for (int d = tid; d < 2048; d += 512) {        // W2 [64][32]
        int j = d >> 5, k = d & 31;
        sW2p[j * INP2 + k] = W2[d];
    }
    for (int d = tid; d < 4096; d += 512) {        // W3 [64][64]
        int j = d >> 6, k = d & 63;
        sW3p[j * INP3 + k] = W3[d];
    }
    for (int d = tid; d < 2048; d += 512) {        // W4 [32][64]
        int j = d >> 6, k = d & 63;
        sW4p[j * INP4 + k] = W4[d];
    }
    if (tid < 32) { sW1[tid] = W1[tid]; sB1[tid] = b1[tid];
                    sB4[tid] = b4[tid]; sW5[tid] = W5[tid]; }
    if (tid < 64) { sB2[tid] = b2[tid]; sB3[tid] = b3[tid]; }
    if (tid == 0) sB5 = b5[0];

    // ---- per-block redundant edge range (t sorted per row)
    float l = 3.4e38f, h = -3.4e38f;
    for (int r = tid; r < nrows; r += 512) {
        l = fminf(l, __ldg(&t[(size_t)r * N_SEQ]));
        h = fmaxf(h, __ldg(&t[(size_t)r * N_SEQ + (N_SEQ - 1)]));
    }
#pragma unroll
    for (int off = 16; off > 0; off >>= 1) {
        l = fminf(l, __shfl_down_sync(m, l, off));
        h = fmaxf(h, __shfl_down_sync(m, h, off));
    }
    if (lane == 0) { s_a[wid] = l; s_b[wid] = h; }
    __syncthreads();
    if (tid == 0) {
        float lo = s_a[0], hi = s_b[0];
#pragma unroll
        for (int w = 1; w < 16; w++) {
            lo = fminf(lo, s_a[w]); hi = fmaxf(hi, s_b[w]);
        }
        float range = hi - lo;
        float hh    = (range > 1e-30f) ? range * (1.0f / TBL_N) : 1.0f;
        float inv_h = (range > 1e-30f) ? (float)TBL_N / range : 0.0f;
        s_lo = lo; s_h = hh;
        if (blockIdx.x == 0) g_range = make_float2(-lo * inv_h, inv_h);
    }
    __syncthreads();

    // ---- MLP: warp wid computes knot kn
    int kn = blockIdx.x * 16 + wid;
    if (kn <= TBL_N) {
        float tv = s_lo + (float)kn * s_h;

        // layer 1: 1 -> 32
        hbuf[wid][0][lane] = splus(fmaf(tv, sW1[lane], sB1[lane]));
        __syncwarp();
        // layer 2: 32 -> 64
        {
            const float4* hv4 = reinterpret_cast<const float4*>(hbuf[wid][0]);
            const float4* w0r = reinterpret_cast<const float4*>(sW2p + lane * INP2);
            const float4* w1r = reinterpret_cast<const float4*>(sW2p + (lane + 32) * INP2);
            float a0 = sB2[lane], a1 = sB2[lane + 32];
#pragma unroll
            for (int k4 = 0; k4 < 8; k4++) {
                float4 hv = hv4[k4];
                float4 w0 = w0r[k4];
                float4 w1 = w1r[k4];
                a0 = fmaf(w0.x, hv.x, a0); a0 = fmaf(w0.y, hv.y, a0);
                a0 = fmaf(w0.z, hv.z, a0); a0 = fmaf(w0.w, hv.w, a0);
                a1 = fmaf(w1.x, hv.x, a1); a1 = fmaf(w1.y, hv.y, a1);
                a1 = fmaf(w1.z, hv.z, a1); a1 = fmaf(w1.w, hv.w, a1);
            }
            hbuf[wid][1][lane]      = splus(a0);
            hbuf[wid][1][lane + 32] = splus(a1);
        }
        __syncwarp();
        // layer 3: 64 -> 64
        {
            const float4* hv4 = reinterpret_cast<const float4*>(hbuf[wid][1]);
            const float4* w0r = reinterpret_cast<const float4*>(sW3p + lane * INP3);
            const float4* w1r = reinterpret_cast<const float4*>(sW3p + (lane + 32) * INP3);
            float a0 = sB3[lane], a1 = sB3[lane + 32];
#pragma unroll
            for (int k4 = 0; k4 < 16; k4++) {
                float4 hv = hv4[k4];
                float4 w0 = w0r[k4];
                float4 w1 = w1r[k4];
                a0 = fmaf(w0.x, hv.x, a0); a0 = fmaf(w0.y, hv.y, a0);
                a0 = fmaf(w0.z, hv.z, a0); a0 = fmaf(w0.w, hv.w, a0);
                a1 = fmaf(w1.x, hv.x, a1); a1 = fmaf(w1.y, hv.y, a1);
                a1 = fmaf(w1.z, hv.z, a1); a1 = fmaf(w1.w, hv.w, a1);
            }
            hbuf[wid][0][lane]      = splus(a0);
            hbuf[wid][0][lane + 32] = splus(a1);
        }
        __syncwarp();
        // layer 4: 64 -> 32
        float h4;
        {
            const float4* hv4 = reinterpret_cast<const float4*>(hbuf[wid][0]);
            const float4* w0r = reinterpret_cast<const float4*>(sW4p + lane * INP4);
            float a0 = sB4[lane];
#pragma unroll
            for (int k4 = 0; k4 < 16; k4++) {
                float4 hv = hv4[k4];
                float4 w0 = w0r[k4];
                a0 = fmaf(w0.x, hv.x, a0); a0 = fmaf(w0.y, hv.y, a0);
                a0 = fmaf(w0.z, hv.z, a0); a0 = fmaf(w0.w, hv.w, a0);
            }
            h4 = splus(a0);
        }
        // layer 5: 32 -> 1 (warp reduce)
        float p = h4 * sW5[lane];
#pragma unroll
        for (int off = 16; off > 0; off >>= 1)
            p += __shfl_xor_sync(m, p, off);

        if (lane == 0) {
            float v = splus(p + sB5) + 1.0f;
            float* tbl = reinterpret_cast<float*>(g_tbl2);
            if (kn < TBL_N) tbl[2 * kn] = v;
            if (kn >= 1)    tbl[2 * (kn - 1) + 1] = v;
            __threadfence();                 // publish before the counter
        }
    }
    __syncthreads();

    // ---- last block: antiderivative as per-interval polynomial in u --------
    if (tid == 0) {
        int old = atomicAdd(&g_cnt, 1);
        s_last = (old == nblk - 1);
    }
    __syncthreads();
    if (!s_last) return;

    if (tid < 64) {                          // 2 warps handle TBL_N = 64
        float hh = s_h;
        float2 f0 = __ldcg(&g_tbl2[tid]);
        float a0 = hh * f0.x, b0 = 0.5f * hh * (f0.y - f0.x);
        float s0 = a0 + b0;

        // inclusive scan across 64 threads (2 warps)
        float v = s0;
#pragma unroll
        for (int off = 1; off < 32; off <<= 1) {
            float n = __shfl_up_sync(m, v, off);
            if (lane >= off) v += n;
        }
        if (lane == 31) s_a[wid] = v;
        __syncwarp();
        __threadfence_block();
        // warp 1 adds warp 0's total (s_a[0] written by warp 0 lane 31)
        if (wid == 1) {
            while (true) {                    // cheap intra-block handshake:
                __syncwarp();                 // both warps under same barrier
                break;
            }
        }
        __syncthreads();                      // simple + safe across 2 warps
        float base = (wid == 1) ? s_a[0] : 0.0f;
        float incl = base + v;
        float excl = incl - s0;

        float fi = (float)tid;
        // P(u) = A + B*u + C*u^2 ; frac = u - i folded in
        float A = fmaf(b0, fi * fi, fmaf(-a0, fi, excl));
        float B = fmaf(-2.0f * b0, fi, a0);
        g_coef[tid] = make_float4(A, B, b0, 0.0f);
        if (tid == TBL_N - 1) {
            // pad entry: linear extension from u = TBL_N with slope h*f(hi)
            float a_pad = hh * f0.y;
            g_coef[TBL_N] = make_float4(fmaf(-a_pad, (float)TBL_N, incl),
                                        a_pad, 0.0f, 0.0f);
        }
    } else {
        __syncthreads();                      // match the scan's barrier
    }
    __syncthreads();
    if (tid == 0) g_cnt = 0;                 // reset for next graph replay
}

// -------------------------- kernel 2: map (PDL secondary) -------------------
#define S_THREADS 512

__device__ __forceinline__ float evalGs(float u,
                                        const float4* __restrict__ scoef) {
    int i = (int)u;                          // u in [0, TBL_N + eps)
    float4 c = scoef[i];                     // LDS.128, broadcast-friendly
    return fmaf(u, fmaf(u, c.z, c.y), c.x);
}

__global__ __launch_bounds__(S_THREADS) void map_kernel(
    const float* __restrict__ t, float* __restrict__ out)
{
    __shared__ __align__(16) float4 scoef[TBL_N + 1];   // 1.04 KB

    int gid = blockIdx.x;
    int row = gid >> 2;                       // NCHUNK = 4
    size_t base = (size_t)row * N_SEQ + (size_t)(gid & 3) * CHUNK;
    int tid = threadIdx.x;

    // ---- prefetch everything that does NOT depend on the table -------------
    const float4* t4 = reinterpret_cast<const float4*>(t + base);
    float t0 = __ldg(&t[(size_t)row * N_SEQ]);     // row anchor
    float4 v0 = t4[tid];
    float4 v1 = t4[tid + S_THREADS];

    // ---- wait for table_kernel completion (PDL) -----------------------------
    cudaGridDependencySynchronize();

    float2 rg = g_range;
    float c0 = rg.x, inv_h = rg.y;

    // G0 from GLOBAL coef (overlaps the smem staging below)
    float u0 = fmaf(t0, inv_h, c0);
    float4 cg = __ldg(&g_coef[(int)u0]);
    float G0 = fmaf(u0, fmaf(u0, cg.z, cg.y), cg.x);

    // stage coefficient table into shared memory
    if (tid <= TBL_N) scoef[tid] = g_coef[tid];
    __syncthreads();

    float4* o4 = reinterpret_cast<float4*>(out + base);
    float4 o;
    o.x = evalGs(fmaf(v0.x, inv_h, c0), scoef) - G0;
    o.y = evalGs(fmaf(v0.y, inv_h, c0), scoef) - G0;
    o.z = evalGs(fmaf(v0.z, inv_h, c0), scoef) - G0;
    o.w = evalGs(fmaf(v0.w, inv_h, c0), scoef) - G0;
    o4[tid] = o;
    o.x = evalGs(fmaf(v1.x, inv_h, c0), scoef) - G0;
    o.y = evalGs(fmaf(v1.y, inv_h, c0), scoef) - G0;
    o.z = evalGs(fmaf(v1.z, inv_h, c0), scoef) - G0;
    o.w = evalGs(fmaf(v1.w, inv_h, c0), scoef) - G0;
    o4[tid + S_THREADS] = o;
}

// ----------------------------------------------------------------------------
extern "C" void kernel_launch(void* const* d_in, const int* in_sizes, int n_in,
                              void* d_out, int out_size) {
    const float* t  = (const float*)d_in[0];
    const float* W1 = (const float*)d_in[1];
    const float* b1 = (const float*)d_in[2];
    const float* W2 = (const float*)d_in[3];
    const float* b2 = (const float*)d_in[4];
    const float* W3 = (const float*)d_in[5];
    const float* b3 = (const float*)d_in[6];
    const float* W4 = (const float*)d_in[7];
    const float* b4 = (const float*)d_in[8];
    const float* W5 = (const float*)d_in[9];
    const float* b5 = (const float*)d_in[10];
    float* out = (float*)d_out;

    int total = in_sizes[0];          // B * N
    int nrows = total / N_SEQ;        // B

    table_kernel<<<NTB, 512>>>(t, nrows, W1, b1, W2, b2, W3, b3,
                               W4, b4, W5, b5, NTB);

    // map: programmatic dependent launch — overlaps its t prefetch with table
    cudaLaunchConfig_t cfg = {};
    cfg.gridDim  = dim3((unsigned)(total / CHUNK), 1, 1);
    cfg.blockDim = dim3(S_THREADS, 1, 1);
    cudaLaunchAttribute attrs[1];
    attrs[0].id = cudaLaunchAttributeProgrammaticStreamSerialization;
    attrs[0].val.programmaticStreamSerializationAllowed = 1;
    cfg.attrs = attrs;
    cfg.numAttrs = 1;
    cudaLaunchKernelEx(&cfg, map_kernel, t, out);
}